// round 2
// baseline (speedup 1.0000x reference)
#include <cuda_runtime.h>
#include <cuda_bf16.h>
#include <cstdint>

// Problem constants
constexpr int Bc   = 2;
constexpr int Sc   = 2048;
constexpr int Dc   = 1024;
constexpr int Hc   = 16;
constexpr int HKVc = 4;
constexpr int DKc  = 64;      // D / H
constexpr int KVD  = HKVc * DKc; // 256

// Scratch (device globals: allocation-free)
__device__ float g_Qp[Bc * Sc * Dc];       // projected Q  [B,S,D]
__device__ float g_Kp[Bc * Sc * KVD];      // projected K  [B,S,256]
__device__ float g_Vp[Bc * Sc * KVD];      // projected V  [B,S,256]
__device__ float g_AO[Bc * Sc * Dc];       // attention out [B,S,D]

// ---------------------------------------------------------------------------
// Tiled SGEMM with bias:  C[M,N] = A[M,K] @ B[K,N] + bias[N]
// BM=BN=64, BK=16, 256 threads, 4x4 per thread. M,N,K all divisible.
// ---------------------------------------------------------------------------
__global__ __launch_bounds__(256) void sgemm_bias_kernel(
    const float* __restrict__ A, const float* __restrict__ B,
    const float* __restrict__ bias, float* __restrict__ C,
    int M, int N, int K)
{
    __shared__ float As[16][64 + 1];   // [k][m], padded
    __shared__ float Bs[16][64];       // [k][n]

    const int tid = threadIdx.x;
    const int bn = blockIdx.x * 64;
    const int bm = blockIdx.y * 64;
    const int tx = tid & 15;           // 0..15 -> col group
    const int ty = tid >> 4;           // 0..15 -> row group

    float acc[4][4];
    #pragma unroll
    for (int i = 0; i < 4; i++)
        #pragma unroll
        for (int j = 0; j < 4; j++) acc[i][j] = 0.f;

    for (int k0 = 0; k0 < K; k0 += 16) {
        // Load A tile: 64 rows x 16 k. tid -> (kk = tid%16, mm = tid/16 + 16*r)
        #pragma unroll
        for (int r = 0; r < 4; r++) {
            int mm = (tid >> 4) + r * 16;
            int kk = tid & 15;
            As[kk][mm] = A[(size_t)(bm + mm) * K + k0 + kk];
        }
        // Load B tile: 16 k x 64 cols. tid -> (kk = tid/64 + 4*r, nn = tid%64)
        #pragma unroll
        for (int r = 0; r < 4; r++) {
            int kk = (tid >> 6) + r * 4;
            int nn = tid & 63;
            Bs[kk][nn] = B[(size_t)(k0 + kk) * N + bn + nn];
        }
        __syncthreads();

        #pragma unroll
        for (int kk = 0; kk < 16; kk++) {
            float a[4], b[4];
            #pragma unroll
            for (int i = 0; i < 4; i++) a[i] = As[kk][ty * 4 + i];
            #pragma unroll
            for (int j = 0; j < 4; j++) b[j] = Bs[kk][tx * 4 + j];
            #pragma unroll
            for (int i = 0; i < 4; i++)
                #pragma unroll
                for (int j = 0; j < 4; j++)
                    acc[i][j] = fmaf(a[i], b[j], acc[i][j]);
        }
        __syncthreads();
    }

    #pragma unroll
    for (int i = 0; i < 4; i++) {
        int row = bm + ty * 4 + i;
        #pragma unroll
        for (int j = 0; j < 4; j++) {
            int col = bn + tx * 4 + j;
            C[(size_t)row * N + col] = acc[i][j] + bias[col];
        }
    }
}

// ---------------------------------------------------------------------------
// Flash attention (fp32, causal, GQA).
// grid: (S/64, H, B); block: 256 threads.
// Each q-row handled by 4 consecutive lanes (sub = tid&3), each owning 16 of
// the 64 dk columns. Online softmax; scores reduced via shfl within the quad.
// ---------------------------------------------------------------------------
constexpr int BQ = 64;
constexpr int BK = 64;

__global__ __launch_bounds__(256, 1) void attn_kernel(
    const float* __restrict__ Qp, const float* __restrict__ Kp,
    const float* __restrict__ Vp, float* __restrict__ AO)
{
    __shared__ float Ks[BK][DKc];   // 16 KB
    __shared__ float Vs[BK][DKc];   // 16 KB

    const int qtile = blockIdx.x;
    const int h     = blockIdx.y;
    const int b     = blockIdx.z;
    const int hkv   = h >> 2;       // RATIO = 4
    const int tid   = threadIdx.x;
    const int row   = tid >> 2;     // 0..63
    const int sub   = tid & 3;      // 0..3
    const int q_idx = qtile * BQ + row;
    const float scale = 0.125f;     // 1/sqrt(64)

    float q[16], acc[16];
    const float* qptr = Qp + ((size_t)(b * Sc + q_idx)) * Dc + h * DKc + sub * 16;
    #pragma unroll
    for (int i = 0; i < 16; i++) { q[i] = qptr[i]; acc[i] = 0.f; }

    float m = -1e30f, l = 0.f;

    const int kend = (qtile + 1) * BQ;   // causal: skip tiles fully above diag
    for (int k0 = 0; k0 < kend; k0 += BK) {
        __syncthreads();
        // load K and V tiles [64 x 64] as float4 (1024 float4, 4 per thread)
        const float4* Kg = (const float4*)(Kp + ((size_t)(b * Sc + k0)) * KVD + hkv * DKc);
        const float4* Vg = (const float4*)(Vp + ((size_t)(b * Sc + k0)) * KVD + hkv * DKc);
        #pragma unroll
        for (int t = 0; t < 4; t++) {
            int idx = tid + t * 256;     // float4 index 0..1023
            int j   = idx >> 4;          // k row
            int d4  = idx & 15;
            ((float4*)Ks)[j * 16 + d4] = Kg[(size_t)j * (KVD / 4) + d4];
            ((float4*)Vs)[j * 16 + d4] = Vg[(size_t)j * (KVD / 4) + d4];
        }
        __syncthreads();

        // scores for this row (each quad redundantly holds full s[] after shfl)
        float s[BK];
        #pragma unroll
        for (int j = 0; j < BK; j++) {
            float p = 0.f;
            #pragma unroll
            for (int i = 0; i < 16; i++)
                p = fmaf(q[i], Ks[j][sub * 16 + i], p);
            p += __shfl_xor_sync(0xffffffffu, p, 1);
            p += __shfl_xor_sync(0xffffffffu, p, 2);
            s[j] = (k0 + j > q_idx) ? -1e30f : p * scale;
        }

        // online softmax update
        float mnew = m;
        #pragma unroll
        for (int j = 0; j < BK; j++) mnew = fmaxf(mnew, s[j]);
        float corr = __expf(m - mnew);
        l *= corr;
        #pragma unroll
        for (int i = 0; i < 16; i++) acc[i] *= corr;
        #pragma unroll
        for (int j = 0; j < BK; j++) {
            float p = __expf(s[j] - mnew);
            l += p;
            #pragma unroll
            for (int i = 0; i < 16; i++)
                acc[i] = fmaf(p, Vs[j][sub * 16 + i], acc[i]);
        }
        m = mnew;
    }

    const float inv = 1.f / l;
    float* op = AO + ((size_t)(b * Sc + q_idx)) * Dc + h * DKc + sub * 16;
    #pragma unroll
    for (int i = 0; i < 16; i++) op[i] = acc[i] * inv;
}

// ---------------------------------------------------------------------------
// Launch
// ---------------------------------------------------------------------------
extern "C" void kernel_launch(void* const* d_in, const int* in_sizes, int n_in,
                              void* d_out, int out_size)
{
    const float* q  = (const float*)d_in[0];
    const float* k  = (const float*)d_in[1];
    const float* v  = (const float*)d_in[2];
    // d_in[3] = mask (causal, known statically — unused)
    const float* Wq = (const float*)d_in[4];
    const float* bq = (const float*)d_in[5];
    const float* Wk = (const float*)d_in[6];
    const float* bk = (const float*)d_in[7];
    const float* Wv = (const float*)d_in[8];
    const float* bv = (const float*)d_in[9];
    const float* Wo = (const float*)d_in[10];
    const float* bo = (const float*)d_in[11];
    float* out = (float*)d_out;

    float *Qp, *Kp, *Vp, *AO;
    cudaGetSymbolAddress((void**)&Qp, g_Qp);
    cudaGetSymbolAddress((void**)&Kp, g_Kp);
    cudaGetSymbolAddress((void**)&Vp, g_Vp);
    cudaGetSymbolAddress((void**)&AO, g_AO);

    const int M = Bc * Sc;   // 4096

    // Q projection: [4096,1024] @ [1024,1024]
    {
        dim3 grid(Dc / 64, M / 64);
        sgemm_bias_kernel<<<grid, 256>>>(q, Wq, bq, Qp, M, Dc, Dc);
    }
    // K projection: [4096,1024] @ [1024,256]
    {
        dim3 grid(KVD / 64, M / 64);
        sgemm_bias_kernel<<<grid, 256>>>(k, Wk, bk, Kp, M, KVD, Dc);
    }
    // V projection
    {
        dim3 grid(KVD / 64, M / 64);
        sgemm_bias_kernel<<<grid, 256>>>(v, Wv, bv, Vp, M, KVD, Dc);
    }
    // Attention
    {
        dim3 grid(Sc / BQ, Hc, Bc);
        attn_kernel<<<grid, 256>>>(Qp, Kp, Vp, AO);
    }
    // Output projection: [4096,1024] @ [1024,1024] -> d_out
    {
        dim3 grid(Dc / 64, M / 64);
        sgemm_bias_kernel<<<grid, 256>>>(AO, Wo, bo, out, M, Dc, Dc);
    }
}

// round 3
// speedup vs baseline: 2.0188x; 2.0188x over previous
#include <cuda_runtime.h>
#include <cuda_bf16.h>
#include <cstdint>

// Problem constants
constexpr int Bc   = 2;
constexpr int Sc   = 2048;
constexpr int Dc   = 1024;
constexpr int Hc   = 16;
constexpr int HKVc = 4;
constexpr int DKc  = 64;         // D / H
constexpr int KVD  = HKVc * DKc; // 256

// Scratch (device globals: allocation-free)
__device__ float g_Qp[Bc * Sc * Dc];
__device__ float g_Kp[Bc * Sc * KVD];
__device__ float g_Vp[Bc * Sc * KVD];
__device__ float g_AO[Bc * Sc * Dc];

// ---------------------------------------------------------------------------
// SGEMM v2: C[M,N] = A[M,K] @ B[K,N] + bias[N]
// BM=BN=128, BK=16, 256 threads, 8x8 microtile (split 4+4 for bank-conflict-
// free float4 shared reads). M%128==0, N%128==0, K%16==0 assumed.
// ---------------------------------------------------------------------------
__global__ __launch_bounds__(256) void sgemm_bias_v2(
    const float* __restrict__ A, const float* __restrict__ B,
    const float* __restrict__ bias, float* __restrict__ C,
    int M, int N, int K)
{
    __shared__ float As[16][128];   // [k][m] (transposed on load)
    __shared__ float Bs[16][128];   // [k][n]

    const int tid = threadIdx.x;
    const int bn  = blockIdx.x * 128;
    const int bm  = blockIdx.y * 128;
    const int tx  = tid & 15;       // 16 col-groups
    const int ty  = tid >> 4;       // 16 row-groups

    float acc[8][8];
    #pragma unroll
    for (int i = 0; i < 8; i++)
        #pragma unroll
        for (int j = 0; j < 8; j++) acc[i][j] = 0.f;

    for (int k0 = 0; k0 < K; k0 += 16) {
        // A tile: 128 rows x 16 k  = 512 float4, transpose into As[k][m]
        #pragma unroll
        for (int t = 0; t < 2; t++) {
            int f   = tid + t * 256;
            int row = f >> 2;
            int c4  = (f & 3) << 2;
            float4 v = *(const float4*)&A[(size_t)(bm + row) * K + k0 + c4];
            As[c4 + 0][row] = v.x;
            As[c4 + 1][row] = v.y;
            As[c4 + 2][row] = v.z;
            As[c4 + 3][row] = v.w;
        }
        // B tile: 16 k x 128 n = 512 float4, direct
        #pragma unroll
        for (int t = 0; t < 2; t++) {
            int f  = tid + t * 256;
            int kk = f >> 5;
            int n4 = (f & 31) << 2;
            *(float4*)&Bs[kk][n4] = *(const float4*)&B[(size_t)(k0 + kk) * N + bn + n4];
        }
        __syncthreads();

        #pragma unroll
        for (int kk = 0; kk < 16; kk++) {
            float a[8], b[8];
            *(float4*)&a[0] = *(float4*)&As[kk][ty * 4];
            *(float4*)&a[4] = *(float4*)&As[kk][64 + ty * 4];
            *(float4*)&b[0] = *(float4*)&Bs[kk][tx * 4];
            *(float4*)&b[4] = *(float4*)&Bs[kk][64 + tx * 4];
            #pragma unroll
            for (int i = 0; i < 8; i++)
                #pragma unroll
                for (int j = 0; j < 8; j++)
                    acc[i][j] = fmaf(a[i], b[j], acc[i][j]);
        }
        __syncthreads();
    }

    // epilogue
    #pragma unroll
    for (int i = 0; i < 8; i++) {
        int row = bm + ((i < 4) ? (ty * 4 + i) : (64 + ty * 4 + (i - 4)));
        int c0  = bn + tx * 4;
        int c1  = bn + 64 + tx * 4;
        float4 o0, o1;
        o0.x = acc[i][0] + bias[c0 + 0];
        o0.y = acc[i][1] + bias[c0 + 1];
        o0.z = acc[i][2] + bias[c0 + 2];
        o0.w = acc[i][3] + bias[c0 + 3];
        o1.x = acc[i][4] + bias[c1 + 0];
        o1.y = acc[i][5] + bias[c1 + 1];
        o1.z = acc[i][6] + bias[c1 + 2];
        o1.w = acc[i][7] + bias[c1 + 3];
        *(float4*)&C[(size_t)row * N + c0] = o0;
        *(float4*)&C[(size_t)row * N + c1] = o1;
    }
}

// ---------------------------------------------------------------------------
// Flash attention v2 (fp32, causal, GQA), register-tiled.
// grid: (S/64, H, B); 256 threads as 16x16; each thread owns a 4x4 microtile
// of the 64x64 score tile and a 4(row)x4(col) slice of the output.
// ---------------------------------------------------------------------------
constexpr int BQ = 64;
constexpr int BK = 64;

__global__ __launch_bounds__(256, 1) void attn_v2(
    const float* __restrict__ Qp, const float* __restrict__ Kp,
    const float* __restrict__ Vp, float* __restrict__ AO)
{
    __shared__ float Qs[DKc][BQ];   // Q^T  [dk][row]
    __shared__ float Ks[DKc][BK];   // K^T  [dk][col]
    __shared__ float Vs[BK][DKc];   // V    [col][dk]
    __shared__ float Ps[BK][BQ];    // P^T  [col][row]

    const int qtile = blockIdx.x;
    const int h     = blockIdx.y;
    const int b     = blockIdx.z;
    const int hkv   = h >> 2;
    const int tid   = threadIdx.x;
    const int tx    = tid & 15;
    const int ty    = tid >> 4;
    const float scale = 0.125f;     // 1/sqrt(64)

    // ---- load Q tile (transposed) : 64x64 floats = 1024 float4, 4/thread
    {
        #pragma unroll
        for (int t = 0; t < 4; t++) {
            int f   = tid + t * 256;
            int row = f >> 4;
            int c4  = (f & 15) << 2;
            float4 v = *(const float4*)&Qp[((size_t)(b * Sc + qtile * BQ + row)) * Dc + h * DKc + c4];
            Qs[c4 + 0][row] = v.x;
            Qs[c4 + 1][row] = v.y;
            Qs[c4 + 2][row] = v.z;
            Qs[c4 + 3][row] = v.w;
        }
    }

    float o[4][4];
    float m[4], l[4];
    #pragma unroll
    for (int i = 0; i < 4; i++) {
        m[i] = -1e30f; l[i] = 0.f;
        #pragma unroll
        for (int d = 0; d < 4; d++) o[i][d] = 0.f;
    }

    const int ntiles = qtile + 1;   // causal
    for (int t0 = 0; t0 < ntiles; t0++) {
        const int k0 = t0 * BK;
        __syncthreads();   // previous iteration's stage3 done before reload

        // ---- load K (transposed) + V (direct)
        #pragma unroll
        for (int t = 0; t < 4; t++) {
            int f   = tid + t * 256;
            int row = f >> 4;
            int c4  = (f & 15) << 2;
            size_t base = ((size_t)(b * Sc + k0 + row)) * KVD + hkv * DKc + c4;
            float4 kv = *(const float4*)&Kp[base];
            Ks[c4 + 0][row] = kv.x;
            Ks[c4 + 1][row] = kv.y;
            Ks[c4 + 2][row] = kv.z;
            Ks[c4 + 3][row] = kv.w;
            *(float4*)&Vs[row][c4] = *(const float4*)&Vp[base];
        }
        __syncthreads();

        // ---- stage 1: S = Q K^T  (64x64x64, 4x4 per thread)
        float s[4][4];
        #pragma unroll
        for (int i = 0; i < 4; i++)
            #pragma unroll
            for (int j = 0; j < 4; j++) s[i][j] = 0.f;

        #pragma unroll 16
        for (int kk = 0; kk < DKc; kk++) {
            float a[4], bb[4];
            *(float4*)&a[0]  = *(float4*)&Qs[kk][ty * 4];
            *(float4*)&bb[0] = *(float4*)&Ks[kk][tx * 4];
            #pragma unroll
            for (int i = 0; i < 4; i++)
                #pragma unroll
                for (int j = 0; j < 4; j++)
                    s[i][j] = fmaf(a[i], bb[j], s[i][j]);
        }

        // ---- scale + causal mask (only on diagonal tile)
        if (t0 == qtile) {
            #pragma unroll
            for (int i = 0; i < 4; i++) {
                int row = qtile * BQ + ty * 4 + i;
                #pragma unroll
                for (int j = 0; j < 4; j++) {
                    int col = k0 + tx * 4 + j;
                    s[i][j] = (col > row) ? -1e30f : s[i][j] * scale;
                }
            }
        } else {
            #pragma unroll
            for (int i = 0; i < 4; i++)
                #pragma unroll
                for (int j = 0; j < 4; j++) s[i][j] *= scale;
        }

        // ---- online softmax (row groups = 16 lanes sharing ty)
        #pragma unroll
        for (int i = 0; i < 4; i++) {
            float mt = fmaxf(fmaxf(s[i][0], s[i][1]), fmaxf(s[i][2], s[i][3]));
            #pragma unroll
            for (int off = 1; off < 16; off <<= 1)
                mt = fmaxf(mt, __shfl_xor_sync(0xffffffffu, mt, off));
            float mn   = fmaxf(m[i], mt);
            float corr = __expf(m[i] - mn);
            float ps = 0.f;
            #pragma unroll
            for (int j = 0; j < 4; j++) {
                float p = __expf(s[i][j] - mn);
                s[i][j] = p;
                ps += p;
            }
            #pragma unroll
            for (int off = 1; off < 16; off <<= 1)
                ps += __shfl_xor_sync(0xffffffffu, ps, off);
            l[i] = l[i] * corr + ps;
            m[i] = mn;
            #pragma unroll
            for (int d = 0; d < 4; d++) o[i][d] *= corr;
        }

        // ---- stage 2: stage P through shared (transposed)
        #pragma unroll
        for (int i = 0; i < 4; i++)
            #pragma unroll
            for (int j = 0; j < 4; j++)
                Ps[tx * 4 + j][ty * 4 + i] = s[i][j];
        __syncthreads();

        // ---- stage 3: O += P V (64x64x64, 4x4 per thread)
        #pragma unroll 16
        for (int j = 0; j < BK; j++) {
            float a[4], bb[4];
            *(float4*)&a[0]  = *(float4*)&Ps[j][ty * 4];
            *(float4*)&bb[0] = *(float4*)&Vs[j][tx * 4];
            #pragma unroll
            for (int i = 0; i < 4; i++)
                #pragma unroll
                for (int d = 0; d < 4; d++)
                    o[i][d] = fmaf(a[i], bb[d], o[i][d]);
        }
    }

    // ---- epilogue
    #pragma unroll
    for (int i = 0; i < 4; i++) {
        float inv = 1.f / l[i];
        float4 v;
        v.x = o[i][0] * inv;
        v.y = o[i][1] * inv;
        v.z = o[i][2] * inv;
        v.w = o[i][3] * inv;
        *(float4*)&AO[((size_t)(b * Sc + qtile * BQ + ty * 4 + i)) * Dc + h * DKc + tx * 4] = v;
    }
}

// ---------------------------------------------------------------------------
// Launch
// ---------------------------------------------------------------------------
extern "C" void kernel_launch(void* const* d_in, const int* in_sizes, int n_in,
                              void* d_out, int out_size)
{
    const float* q  = (const float*)d_in[0];
    const float* k  = (const float*)d_in[1];
    const float* v  = (const float*)d_in[2];
    // d_in[3] = mask (causal, static — unused)
    const float* Wq = (const float*)d_in[4];
    const float* bq = (const float*)d_in[5];
    const float* Wk = (const float*)d_in[6];
    const float* bk = (const float*)d_in[7];
    const float* Wv = (const float*)d_in[8];
    const float* bv = (const float*)d_in[9];
    const float* Wo = (const float*)d_in[10];
    const float* bo = (const float*)d_in[11];
    float* out = (float*)d_out;

    float *Qp, *Kp, *Vp, *AO;
    cudaGetSymbolAddress((void**)&Qp, g_Qp);
    cudaGetSymbolAddress((void**)&Kp, g_Kp);
    cudaGetSymbolAddress((void**)&Vp, g_Vp);
    cudaGetSymbolAddress((void**)&AO, g_AO);

    const int M = Bc * Sc;   // 4096

    // Q projection: [4096,1024] @ [1024,1024]
    {
        dim3 grid(Dc / 128, M / 128);
        sgemm_bias_v2<<<grid, 256>>>(q, Wq, bq, Qp, M, Dc, Dc);
    }
    // K projection: [4096,1024] @ [1024,256]
    {
        dim3 grid(KVD / 128, M / 128);
        sgemm_bias_v2<<<grid, 256>>>(k, Wk, bk, Kp, M, KVD, Dc);
    }
    // V projection
    {
        dim3 grid(KVD / 128, M / 128);
        sgemm_bias_v2<<<grid, 256>>>(v, Wv, bv, Vp, M, KVD, Dc);
    }
    // Attention
    {
        dim3 grid(Sc / BQ, Hc, Bc);
        attn_v2<<<grid, 256>>>(Qp, Kp, Vp, AO);
    }
    // Output projection -> d_out
    {
        dim3 grid(Dc / 128, M / 128);
        sgemm_bias_v2<<<grid, 256>>>(AO, Wo, bo, out, M, Dc, Dc);
    }
}